// round 1
// baseline (speedup 1.0000x reference)
#include <cuda_runtime.h>
#include <cstdint>

// Problem constants
#define BB   64
#define CC   512
#define NN   3000
#define MAXH 70
#define MAXW 40
#define HW   (MAXH * MAXW)        // 2800
#define TOTAL_OUT ((size_t)BB * CC * HW)   // 91,750,400

// -------- scratch (no allocations allowed) --------
__device__ int g_cell2point[BB * HW];   // -1 = empty
__device__ int g_badflag[BB * HW];      // 1 = some channel hit exactly -1.0f
__device__ int g_swap[BB];
__device__ int g_offr[BB];
__device__ int g_offc[BB];

// -------- 1) per-batch bbox + crop/pad params --------
__global__ void minmax_params_kernel(const int* __restrict__ ys,
                                     const int* __restrict__ xs) {
    int b = blockIdx.x;
    const int* y = ys + b * NN;
    const int* x = xs + b * NN;

    int mny = 0x7fffffff, mnx = 0x7fffffff;
    int mxy = -0x7fffffff, mxx = -0x7fffffff;
    for (int n = threadIdx.x; n < NN; n += blockDim.x) {
        int yy = y[n];
        if (yy > -1) {
            int xx = x[n];
            mny = min(mny, yy); mxy = max(mxy, yy);
            mnx = min(mnx, xx); mxx = max(mxx, xx);
        }
    }
    // warp reduce
    for (int o = 16; o; o >>= 1) {
        mny = min(mny, __shfl_down_sync(0xffffffffu, mny, o));
        mnx = min(mnx, __shfl_down_sync(0xffffffffu, mnx, o));
        mxy = max(mxy, __shfl_down_sync(0xffffffffu, mxy, o));
        mxx = max(mxx, __shfl_down_sync(0xffffffffu, mxx, o));
    }
    __shared__ int s_mny[8], s_mnx[8], s_mxy[8], s_mxx[8];
    int wid = threadIdx.x >> 5, lid = threadIdx.x & 31;
    if (lid == 0) { s_mny[wid] = mny; s_mnx[wid] = mnx; s_mxy[wid] = mxy; s_mxx[wid] = mxx; }
    __syncthreads();
    if (threadIdx.x == 0) {
        int nwarps = (blockDim.x + 31) >> 5;
        for (int w = 1; w < nwarps; w++) {
            mny = min(mny, s_mny[w]); mnx = min(mnx, s_mnx[w]);
            mxy = max(mxy, s_mxy[w]); mxx = max(mxx, s_mxx[w]);
        }
        int h = mxy - mny + 1;
        int w = mxx - mnx + 1;
        int swp = (w > h) ? 1 : 0;
        int H0 = swp ? w : h;
        int W0 = swp ? h : w;
        int hd = H0 - MAXH;
        int wd = W0 - MAXW;
        int cut_top  = (hd > 0) ? (hd + 1) / 2 : 0;
        int pad_top  = (hd > 0) ? 0 : (1 - hd) / 2;
        int cut_left = (wd > 0) ? (wd + 1) / 2 : 0;
        int left_pad = (wd > 0) ? 0 : (1 - wd) / 2;
        // rr = (swp ? x - mnx : y - mny) - cut_top + pad_top  = base + off_r
        g_swap[b] = swp;
        g_offr[b] = -(swp ? mnx : mny) - cut_top + pad_top;
        g_offc[b] = -(swp ? mny : mnx) - cut_left + left_pad;
    }
}

// -------- 2) reset scratch (must run every launch: graph replays) --------
__global__ void init_maps_kernel() {
    int i = blockIdx.x * blockDim.x + threadIdx.x;
    if (i < BB * HW) {
        g_cell2point[i] = -1;
        g_badflag[i] = 0;
    }
}

// -------- 3) scatter point index -> cell map (unique targets by construction) ----
__global__ void scatter_idx_kernel(const int* __restrict__ ys,
                                   const int* __restrict__ xs) {
    int i = blockIdx.x * blockDim.x + threadIdx.x;
    if (i >= BB * NN) return;
    int b = i / NN;
    int n = i - b * NN;
    int y = ys[i];
    if (y <= -1) return;
    int x = xs[i];
    int swp = g_swap[b];
    int r = swp ? x : y;
    int c = swp ? y : x;
    int rr = r + g_offr[b];
    int cc = c + g_offc[b];
    if (rr >= 0 && rr < MAXH && cc >= 0 && cc < MAXW)
        g_cell2point[b * HW + rr * MAXW + cc] = n;
}

// -------- 4) the big gather: writes the whole output, coalesced --------
__global__ void gather_kernel(const float* __restrict__ features,
                              float* __restrict__ out) {
    size_t idx = (size_t)blockIdx.x * blockDim.x + threadIdx.x;   // < TOTAL_OUT, exact grid
    int hw = (int)(idx % HW);
    size_t bc = idx / HW;                 // b*CC + c
    int b = (int)(bc / CC);
    int cell = b * HW + hw;
    int p = g_cell2point[cell];           // L2-resident (716 KB total), coalesced in hw
    float v = 0.0f;
    if (p >= 0) {
        v = __ldg(features + bc * NN + p);   // random within a 12KB row -> L1/L2 absorbed
        if (v == -1.0f) atomicOr(&g_badflag[cell], 1);   // ~never taken
    }
    out[idx] = v;
}

// -------- 5) rare fixup: zero all channels of cells that hit exact -1.0 --------
__global__ void fixup_kernel(float* __restrict__ out) {
    int cell = blockIdx.x * blockDim.x + threadIdx.x;
    if (cell >= BB * HW) return;
    if (g_badflag[cell]) {
        int b = cell / HW;
        int hw = cell - b * HW;
        size_t base = (size_t)b * CC * HW + hw;
        for (int c = 0; c < CC; c++)
            out[base + (size_t)c * HW] = 0.0f;
    }
}

extern "C" void kernel_launch(void* const* d_in, const int* in_sizes, int n_in,
                              void* d_out, int out_size) {
    const float* features = (const float*)d_in[0];   // (B, C, N) fp32
    const int*   ys       = (const int*)d_in[1];     // (B, N) int32
    const int*   xs       = (const int*)d_in[2];     // (B, N) int32
    float* out = (float*)d_out;                      // (B, C, 70, 40) fp32

    minmax_params_kernel<<<BB, 256>>>(ys, xs);
    init_maps_kernel<<<(BB * HW + 255) / 256, 256>>>();
    scatter_idx_kernel<<<(BB * NN + 255) / 256, 256>>>(ys, xs);
    gather_kernel<<<(unsigned)(TOTAL_OUT / 256), 256>>>(features, out);  // exact: 358400 blocks
    fixup_kernel<<<(BB * HW + 255) / 256, 256>>>(out);
}

// round 3
// speedup vs baseline: 2.7556x; 2.7556x over previous
#include <cuda_runtime.h>
#include <cuda_pipeline.h>
#include <cstdint>

// Problem constants
#define BB   64
#define CC   512
#define NN   3000
#define MAXH 70
#define MAXW 40
#define HW   (MAXH * MAXW)        // 2800
#define CPB  8                    // channels per block in gather
#define TOTAL_OUT ((size_t)BB * CC * HW)

// -------- scratch (no allocations allowed) --------
__device__ int g_cell2point[BB * HW];   // -1 = empty
__device__ int g_badflag[BB * HW];      // 1 = some channel hit exactly -1.0f
__device__ int g_swap[BB];
__device__ int g_offr[BB];
__device__ int g_offc[BB];

// -------- 1) per-batch bbox + crop/pad params --------
__global__ void minmax_params_kernel(const int* __restrict__ ys,
                                     const int* __restrict__ xs) {
    int b = blockIdx.x;
    const int* y = ys + b * NN;
    const int* x = xs + b * NN;

    int mny = 0x7fffffff, mnx = 0x7fffffff;
    int mxy = -0x7fffffff, mxx = -0x7fffffff;
    for (int n = threadIdx.x; n < NN; n += blockDim.x) {
        int yy = y[n];
        if (yy > -1) {
            int xx = x[n];
            mny = min(mny, yy); mxy = max(mxy, yy);
            mnx = min(mnx, xx); mxx = max(mxx, xx);
        }
    }
    for (int o = 16; o; o >>= 1) {
        mny = min(mny, __shfl_down_sync(0xffffffffu, mny, o));
        mnx = min(mnx, __shfl_down_sync(0xffffffffu, mnx, o));
        mxy = max(mxy, __shfl_down_sync(0xffffffffu, mxy, o));
        mxx = max(mxx, __shfl_down_sync(0xffffffffu, mxx, o));
    }
    __shared__ int s_mny[8], s_mnx[8], s_mxy[8], s_mxx[8];
    int wid = threadIdx.x >> 5, lid = threadIdx.x & 31;
    if (lid == 0) { s_mny[wid] = mny; s_mnx[wid] = mnx; s_mxy[wid] = mxy; s_mxx[wid] = mxx; }
    __syncthreads();
    if (threadIdx.x == 0) {
        int nwarps = (blockDim.x + 31) >> 5;
        for (int w = 1; w < nwarps; w++) {
            mny = min(mny, s_mny[w]); mnx = min(mnx, s_mnx[w]);
            mxy = max(mxy, s_mxy[w]); mxx = max(mxx, s_mxx[w]);
        }
        int h = mxy - mny + 1;
        int w = mxx - mnx + 1;
        int swp = (w > h) ? 1 : 0;
        int H0 = swp ? w : h;
        int W0 = swp ? h : w;
        int hd = H0 - MAXH;
        int wd = W0 - MAXW;
        int cut_top  = (hd > 0) ? (hd + 1) / 2 : 0;
        int pad_top  = (hd > 0) ? 0 : (1 - hd) / 2;
        int cut_left = (wd > 0) ? (wd + 1) / 2 : 0;
        int left_pad = (wd > 0) ? 0 : (1 - wd) / 2;
        g_swap[b] = swp;
        g_offr[b] = -(swp ? mnx : mny) - cut_top + pad_top;
        g_offc[b] = -(swp ? mny : mnx) - cut_left + left_pad;
    }
}

// -------- 2) reset scratch (graph replays: must reset every launch) --------
__global__ void init_maps_kernel() {
    int i = blockIdx.x * blockDim.x + threadIdx.x;
    if (i < BB * HW) {
        g_cell2point[i] = -1;
        g_badflag[i] = 0;
    }
}

// -------- 3) scatter point index -> cell map (unique targets) --------
__global__ void scatter_idx_kernel(const int* __restrict__ ys,
                                   const int* __restrict__ xs) {
    int i = blockIdx.x * blockDim.x + threadIdx.x;
    if (i >= BB * NN) return;
    int b = i / NN;
    int n = i - b * NN;
    int y = ys[i];
    if (y <= -1) return;
    int x = xs[i];
    int swp = g_swap[b];
    int r = swp ? x : y;
    int c = swp ? y : x;
    int rr = r + g_offr[b];
    int cc = c + g_offc[b];
    if (rr >= 0 && rr < MAXH && cc >= 0 && cc < MAXW)
        g_cell2point[b * HW + rr * MAXW + cc] = n;
}

// -------- 4) smem gather, double-buffered cp.async feature streaming --------
// Block = (b, group of CPB channels). cell2point row cached in smem once.
// Channel k+1's 12KB feature row streams in (cp.async) while channel k is
// gathered from smem and stored with coalesced float4 writes. All GMEM
// traffic is vectorized & coalesced; randomness lives in shared memory.
__global__ __launch_bounds__(256) void gather_smem_kernel(
        const float* __restrict__ features,
        float* __restrict__ out) {
    __shared__ __align__(16) int   s_p[HW];        // 11200 B
    __shared__ __align__(16) float s_f[2][NN];     // 2 x 12000 B

    const int tid = threadIdx.x;
    const int b   = blockIdx.x / (CC / CPB);
    const int cg  = blockIdx.x % (CC / CPB);
    const size_t bc0 = (size_t)b * CC + (size_t)cg * CPB;

    // cache this batch's cell->point map (L2-resident source)
    for (int i = tid; i < HW / 4; i += 256)
        ((int4*)s_p)[i] = ((const int4*)(g_cell2point + b * HW))[i];

    // prologue: async-load channel 0 into buffer 0
    {
        const float4* src = (const float4*)(features + bc0 * NN);
        for (int i = tid; i < NN / 4; i += 256)
            __pipeline_memcpy_async(&((float4*)s_f[0])[i], &src[i], 16);
        __pipeline_commit();
    }

    for (int k = 0; k < CPB; k++) {
        const int cur = k & 1;
        __syncthreads();   // all readers of buffer cur^1 (iter k-1) done; s_p ready at k==0

        if (k + 1 < CPB) { // prefetch next channel into the other buffer
            const float4* src = (const float4*)(features + (bc0 + k + 1) * NN);
            for (int i = tid; i < NN / 4; i += 256)
                __pipeline_memcpy_async(&((float4*)s_f[cur ^ 1])[i], &src[i], 16);
            __pipeline_commit();
            __pipeline_wait_prior(1);    // current buffer's copies landed
        } else {
            __pipeline_wait_prior(0);
        }
        __syncthreads();   // current buffer visible to all threads

        const float* __restrict__ f = s_f[cur];
        float4* __restrict__ dst = (float4*)(out + (bc0 + k) * HW);
        for (int i = tid; i < HW / 4; i += 256) {
            int4 p = ((const int4*)s_p)[i];
            float4 v;
            v.x = (p.x >= 0) ? f[p.x] : 0.0f;
            v.y = (p.y >= 0) ? f[p.y] : 0.0f;
            v.z = (p.z >= 0) ? f[p.z] : 0.0f;
            v.w = (p.w >= 0) ? f[p.w] : 0.0f;
            // exact -1.0f sentinel (expected ~never with N(0,1) data)
            if (v.x == -1.0f) atomicOr(&g_badflag[b * HW + 4 * i + 0], 1);
            if (v.y == -1.0f) atomicOr(&g_badflag[b * HW + 4 * i + 1], 1);
            if (v.z == -1.0f) atomicOr(&g_badflag[b * HW + 4 * i + 2], 1);
            if (v.w == -1.0f) atomicOr(&g_badflag[b * HW + 4 * i + 3], 1);
            dst[i] = v;
        }
    }
}

// -------- 5) rare fixup: zero all channels of cells that hit exact -1.0 ----
__global__ void fixup_kernel(float* __restrict__ out) {
    int cell = blockIdx.x * blockDim.x + threadIdx.x;
    if (cell >= BB * HW) return;
    if (g_badflag[cell]) {
        int b = cell / HW;
        int hw = cell - b * HW;
        size_t base = (size_t)b * CC * HW + hw;
        for (int c = 0; c < CC; c++)
            out[base + (size_t)c * HW] = 0.0f;
    }
}

extern "C" void kernel_launch(void* const* d_in, const int* in_sizes, int n_in,
                              void* d_out, int out_size) {
    const float* features = (const float*)d_in[0];   // (B, C, N) fp32
    const int*   ys       = (const int*)d_in[1];     // (B, N) int32
    const int*   xs       = (const int*)d_in[2];     // (B, N) int32
    float* out = (float*)d_out;                      // (B, C, 70, 40) fp32

    minmax_params_kernel<<<BB, 256>>>(ys, xs);
    init_maps_kernel<<<(BB * HW + 255) / 256, 256>>>();
    scatter_idx_kernel<<<(BB * NN + 255) / 256, 256>>>(ys, xs);
    gather_smem_kernel<<<BB * (CC / CPB), 256>>>(features, out);  // 4096 blocks
    fixup_kernel<<<(BB * HW + 255) / 256, 256>>>(out);
}